// round 8
// baseline (speedup 1.0000x reference)
#include <cuda_runtime.h>
#include <cstdint>

// ---------------------------------------------------------------------------
// VectorQuantizer — bit-exact fp32 reference emulation (validated R6/R7, rel 0):
//   m    = exact fp32 FFMA dot, ascending k, acc from 0
//   c    = warp-butterfly fp32 sum of z^2 (16,8,4,2,1)
//   d2   = fl( fma(m,-2,c) ) + e2,  argmin = first index of min
//   q_st = fl(z + fl(q - z))
// R8: rows-in-f32x2-halves packing (4 rows/thread @ ~116 regs, occ 4 = 16 w/SM),
//     e duplicated in smem, value-only chunk-min epilogue (FMNMX), index
//     resolved by a tiny exact re-scan pass. Output kernel 8 threads/row.
// ---------------------------------------------------------------------------

#define N_ROWS  32768
#define CDIM    32
#define KCODES  8192

#define CTA_MAIN    128
#define ROWS_PER_T  4
#define ROWS_PER_CTA (CTA_MAIN * ROWS_PER_T)             // 512
#define ROWBLOCKS   (N_ROWS / ROWS_PER_CTA)              // 64
#define NSPLITS     9
#define GRID_MAIN   (ROWBLOCKS * NSPLITS)                // 576

#define CODES_PER_CHUNK 128
#define NCHUNKS (KCODES / CODES_PER_CHUNK)               // 64

__device__ __align__(16) float d_eT[CDIM * KCODES];   // eT[i*8192 + k] = emb[k][i]
__device__ __align__(16) float d_e2[KCODES];          // butterfly ||e||^2
__device__ float d_c[N_ROWS];                         // butterfly ||z||^2
__device__ unsigned long long d_skey[NSPLITS * N_ROWS]; // (minbits<<6)|chunk
__device__ int   d_idx[N_ROWS];
__device__ float d_partials[1024];

// ---- packed f32x2 helpers -------------------------------------------------
__device__ __forceinline__ unsigned long long pack2(float lo, float hi) {
    unsigned long long r;
    asm("mov.b64 %0, {%1, %2};" : "=l"(r) : "f"(lo), "f"(hi));
    return r;
}
__device__ __forceinline__ unsigned long long dup2(float x) { return pack2(x, x); }
__device__ __forceinline__ unsigned long long ffma2(unsigned long long a,
                                                    unsigned long long b,
                                                    unsigned long long c) {
    unsigned long long d;
    asm("fma.rn.f32x2 %0, %1, %2, %3;" : "=l"(d) : "l"(a), "l"(b), "l"(c));
    return d;
}
__device__ __forceinline__ unsigned long long fadd2(unsigned long long a,
                                                    unsigned long long b) {
    unsigned long long d;
    asm("add.rn.f32x2 %0, %1, %2;" : "=l"(d) : "l"(a), "l"(b));
    return d;
}
__device__ __forceinline__ void unpack2(unsigned long long v, float& lo, float& hi) {
    asm("mov.b64 {%0, %1}, %2;" : "=f"(lo), "=f"(hi) : "l"(v));
}

// XLA GPU warp row-reduce association: shfl.down butterfly 16,8,4,2,1.
__device__ __forceinline__ float butterfly32(float* a) {
#pragma unroll
    for (int off = 16; off >= 1; off >>= 1)
#pragma unroll
        for (int i = 0; i < 16; i++)
            if (i < off) a[i] = __fadd_rn(a[i], a[i + off]);
    return a[0];
}

// ---- P1: transpose emb + e2 -----------------------------------------------
__global__ void vq_prep_codes(const float* __restrict__ emb) {
    int k = blockIdx.x * blockDim.x + threadIdx.x;
    if (k >= KCODES) return;
    float e[CDIM], a[CDIM];
    const float4* er = (const float4*)(emb + (size_t)k * CDIM);
#pragma unroll
    for (int j = 0; j < 8; j++) {
        float4 v = er[j];
        e[4 * j] = v.x; e[4 * j + 1] = v.y; e[4 * j + 2] = v.z; e[4 * j + 3] = v.w;
    }
#pragma unroll
    for (int i = 0; i < CDIM; i++) a[i] = __fmul_rn(e[i], e[i]);
    d_e2[k] = butterfly32(a);
#pragma unroll
    for (int i = 0; i < CDIM; i++) d_eT[i * KCODES + k] = e[i];
}

// ---- P2: c = butterfly ||z||^2 --------------------------------------------
__global__ void vq_prep_rows(const float* __restrict__ z) {
    int n = blockIdx.x * blockDim.x + threadIdx.x;
    if (n >= N_ROWS) return;
    float a[CDIM];
    const float4* zr = (const float4*)(z + (size_t)n * CDIM);
#pragma unroll
    for (int j = 0; j < 8; j++) {
        float4 v = zr[j];
        a[4 * j]     = __fmul_rn(v.x, v.x);
        a[4 * j + 1] = __fmul_rn(v.y, v.y);
        a[4 * j + 2] = __fmul_rn(v.z, v.z);
        a[4 * j + 3] = __fmul_rn(v.w, v.w);
    }
    d_c[n] = butterfly32(a);
}

// ---- pass 1: 4 rows/thread, per-split per-chunk min value -----------------
__global__ __launch_bounds__(CTA_MAIN, 4) void vq_argmin_kernel(const float* __restrict__ z) {
    __shared__ unsigned long long s_ed[CDIM * CODES_PER_CHUNK]; // {e,e} dup, 32KB
    __shared__ unsigned long long s_e2d[CODES_PER_CHUNK];       // {e2,e2} dup, 1KB

    int tid = threadIdx.x;
    int sp  = blockIdx.x / ROWBLOCKS;    // code split 0..8
    int rb  = blockIdx.x % ROWBLOCKS;
    int rowA = rb * ROWS_PER_CTA + tid;
    int rowB = rowA + CTA_MAIN;
    int rowC = rowB + CTA_MAIN;
    int rowD = rowC + CTA_MAIN;

    int ch_lo = (sp * NCHUNKS) / NSPLITS;
    int ch_hi = ((sp + 1) * NCHUNKS) / NSPLITS;

    // z packed rows-in-halves: zAB[i] = {zA_i, zB_i}
    unsigned long long zAB[CDIM], zCD[CDIM];
    {
        const float4* ra = (const float4*)(z + (size_t)rowA * CDIM);
        const float4* rb4 = (const float4*)(z + (size_t)rowB * CDIM);
        const float4* rc = (const float4*)(z + (size_t)rowC * CDIM);
        const float4* rd = (const float4*)(z + (size_t)rowD * CDIM);
#pragma unroll
        for (int j = 0; j < 8; j++) {
            float4 va = ra[j], vb = rb4[j], vc = rc[j], vd = rd[j];
            zAB[4 * j]     = pack2(va.x, vb.x);
            zAB[4 * j + 1] = pack2(va.y, vb.y);
            zAB[4 * j + 2] = pack2(va.z, vb.z);
            zAB[4 * j + 3] = pack2(va.w, vb.w);
            zCD[4 * j]     = pack2(vc.x, vd.x);
            zCD[4 * j + 1] = pack2(vc.y, vd.y);
            zCD[4 * j + 2] = pack2(vc.z, vd.z);
            zCD[4 * j + 3] = pack2(vc.w, vd.w);
        }
    }
    unsigned long long cAB = pack2(d_c[rowA], d_c[rowB]);
    unsigned long long cCD = pack2(d_c[rowC], d_c[rowD]);
    unsigned long long neg2 = dup2(-2.0f);

    float inf = __int_as_float(0x7f800000);
    float gvA = inf, gvB = inf, gvC = inf, gvD = inf;
    int   gcA = 0, gcB = 0, gcC = 0, gcD = 0;

    for (int ch = ch_lo; ch < ch_hi; ch++) {
        // stage duplicated e: s_ed[i*128 + k] = {e_k[i], e_k[i]}
        for (int t = tid; t < CDIM * 32; t += CTA_MAIN) {
            int i = t >> 5, kq = t & 31;
            float4 v = *(const float4*)(d_eT + i * KCODES + ch * CODES_PER_CHUNK + kq * 4);
            unsigned long long* dst = s_ed + i * CODES_PER_CHUNK + kq * 4;
            dst[0] = dup2(v.x); dst[1] = dup2(v.y);
            dst[2] = dup2(v.z); dst[3] = dup2(v.w);
        }
        if (tid < CODES_PER_CHUNK) s_e2d[tid] = dup2(d_e2[ch * CODES_PER_CHUNK + tid]);
        __syncthreads();

        float mA = inf, mB = inf, mC = inf, mD = inf;
#pragma unroll 1
        for (int g = 0; g < 32; g++) {           // 4 codes per group
            const unsigned long long* pe = s_ed + g * 4;
            unsigned long long ab0 = 0ull, ab1 = 0ull, ab2 = 0ull, ab3 = 0ull;
            unsigned long long cd0 = 0ull, cd1 = 0ull, cd2 = 0ull, cd3 = 0ull;
#pragma unroll
            for (int i = 0; i < CDIM; i++) {     // ascending exact FFMA chains
                unsigned long long e0 = pe[i * 128 + 0];
                unsigned long long e1 = pe[i * 128 + 1];
                unsigned long long e2v = pe[i * 128 + 2];
                unsigned long long e3 = pe[i * 128 + 3];
                ab0 = ffma2(zAB[i], e0, ab0);
                ab1 = ffma2(zAB[i], e1, ab1);
                ab2 = ffma2(zAB[i], e2v, ab2);
                ab3 = ffma2(zAB[i], e3, ab3);
                cd0 = ffma2(zCD[i], e0, cd0);
                cd1 = ffma2(zCD[i], e1, cd1);
                cd2 = ffma2(zCD[i], e2v, cd2);
                cd3 = ffma2(zCD[i], e3, cd3);
            }
            unsigned long long q0 = s_e2d[g * 4 + 0], q1 = s_e2d[g * 4 + 1];
            unsigned long long q2 = s_e2d[g * 4 + 2], q3 = s_e2d[g * 4 + 3];
            // d2 = fl(c - 2m) + e2, per half (exact per row)
            unsigned long long dab0 = fadd2(ffma2(ab0, neg2, cAB), q0);
            unsigned long long dab1 = fadd2(ffma2(ab1, neg2, cAB), q1);
            unsigned long long dab2 = fadd2(ffma2(ab2, neg2, cAB), q2);
            unsigned long long dab3 = fadd2(ffma2(ab3, neg2, cAB), q3);
            unsigned long long dcd0 = fadd2(ffma2(cd0, neg2, cCD), q0);
            unsigned long long dcd1 = fadd2(ffma2(cd1, neg2, cCD), q1);
            unsigned long long dcd2 = fadd2(ffma2(cd2, neg2, cCD), q2);
            unsigned long long dcd3 = fadd2(ffma2(cd3, neg2, cCD), q3);
            float lo, hi;
            unpack2(dab0, lo, hi); mA = fminf(mA, lo); mB = fminf(mB, hi);
            unpack2(dab1, lo, hi); mA = fminf(mA, lo); mB = fminf(mB, hi);
            unpack2(dab2, lo, hi); mA = fminf(mA, lo); mB = fminf(mB, hi);
            unpack2(dab3, lo, hi); mA = fminf(mA, lo); mB = fminf(mB, hi);
            unpack2(dcd0, lo, hi); mC = fminf(mC, lo); mD = fminf(mD, hi);
            unpack2(dcd1, lo, hi); mC = fminf(mC, lo); mD = fminf(mD, hi);
            unpack2(dcd2, lo, hi); mC = fminf(mC, lo); mD = fminf(mD, hi);
            unpack2(dcd3, lo, hi); mC = fminf(mC, lo); mD = fminf(mD, hi);
        }
        // strict < + ascending ch  =>  first chunk achieving the running min
        if (mA < gvA) { gvA = mA; gcA = ch; }
        if (mB < gvB) { gvB = mB; gcB = ch; }
        if (mC < gvC) { gvC = mC; gcC = ch; }
        if (mD < gvD) { gvD = mD; gcD = ch; }
        __syncthreads();
    }
    // monotone key (d2 > 0): value bits then chunk id
    d_skey[(size_t)sp * N_ROWS + rowA] = ((unsigned long long)__float_as_uint(gvA) << 6) | (unsigned)gcA;
    d_skey[(size_t)sp * N_ROWS + rowB] = ((unsigned long long)__float_as_uint(gvB) << 6) | (unsigned)gcB;
    d_skey[(size_t)sp * N_ROWS + rowC] = ((unsigned long long)__float_as_uint(gvC) << 6) | (unsigned)gcC;
    d_skey[(size_t)sp * N_ROWS + rowD] = ((unsigned long long)__float_as_uint(gvD) << 6) | (unsigned)gcD;
}

// ---- pass 2: resolve first index inside the winning chunk (exact) ---------
__global__ __launch_bounds__(256) void vq_resolve(const float* __restrict__ z,
                                                  const float* __restrict__ emb) {
    int lane = threadIdx.x & 31;
    int warp = threadIdx.x >> 5;
    int row  = blockIdx.x * 8 + warp;

    unsigned long long key = 0xFFFFFFFFFFFFFFFFull;
    if (lane < NSPLITS) key = d_skey[(size_t)lane * N_ROWS + row];
#pragma unroll
    for (int off = 16; off >= 1; off >>= 1) {
        unsigned long long o = __shfl_down_sync(0xffffffffu, key, off);
        if (o < key) key = o;
    }
    key = __shfl_sync(0xffffffffu, key, 0);
    float M  = __uint_as_float((unsigned)(key >> 6));
    int   ch = (int)(key & 63u);

    // z row (broadcast loads, L1-resident)
    float zv[CDIM];
    const float4* zr = (const float4*)(z + (size_t)row * CDIM);
#pragma unroll
    for (int j = 0; j < 8; j++) {
        float4 v = zr[j];
        zv[4 * j] = v.x; zv[4 * j + 1] = v.y; zv[4 * j + 2] = v.z; zv[4 * j + 3] = v.w;
    }
    float c = d_c[row];

    int cand = 0x7FFFFFFF;
#pragma unroll
    for (int t = 3; t >= 0; t--) {                  // descending: keep smallest k
        int k = ch * CODES_PER_CHUNK + lane * 4 + t;
        const float4* er = (const float4*)(emb + (size_t)k * CDIM);
        float m = 0.f;
#pragma unroll
        for (int j = 0; j < 8; j++) {               // same ascending exact chain
            float4 v = er[j];
            m = __fmaf_rn(zv[4 * j], v.x, m);
            m = __fmaf_rn(zv[4 * j + 1], v.y, m);
            m = __fmaf_rn(zv[4 * j + 2], v.z, m);
            m = __fmaf_rn(zv[4 * j + 3], v.w, m);
        }
        float d2 = __fadd_rn(__fmaf_rn(m, -2.0f, c), d_e2[k]);
        if (d2 <= M) cand = k;                      // min value == M exists here
    }
#pragma unroll
    for (int off = 16; off >= 1; off >>= 1)
        cand = min(cand, __shfl_down_sync(0xffffffffu, cand, off));
    if (lane == 0) d_idx[row] = cand;
}

// ---- K3: 8 threads/row — q_st, idx, loss partials -------------------------
__global__ void vq_output_kernel(const float* __restrict__ z,
                                 const float* __restrict__ emb,
                                 float* __restrict__ out) {
    __shared__ float warpsum[8];
    int gt = blockIdx.x * 256 + threadIdx.x;
    int n = gt >> 3, j = gt & 7;
    int k = d_idx[n];
    float4 e = ((const float4*)(emb + (size_t)k * CDIM))[j];
    float4 zv = ((const float4*)(z + (size_t)n * CDIM))[j];
    float dx = __fadd_rn(e.x, -zv.x), dy = __fadd_rn(e.y, -zv.y);
    float dz = __fadd_rn(e.z, -zv.z), dw = __fadd_rn(e.w, -zv.w);
    float4 q;
    q.x = __fadd_rn(zv.x, dx); q.y = __fadd_rn(zv.y, dy);
    q.z = __fadd_rn(zv.z, dz); q.w = __fadd_rn(zv.w, dw);
    ((float4*)(out + (size_t)n * CDIM))[j] = q;
    if (j == 0) out[(size_t)N_ROWS * CDIM + 2 + n] = (float)k;

    float s = dx * dx + dy * dy + dz * dz + dw * dw;
    int lane = threadIdx.x & 31, wid = threadIdx.x >> 5;
#pragma unroll
    for (int o = 16; o > 0; o >>= 1)
        s += __shfl_down_sync(0xffffffffu, s, o);
    if (lane == 0) warpsum[wid] = s;
    __syncthreads();
    if (wid == 0) {
        float v = (lane < 8) ? warpsum[lane] : 0.f;
#pragma unroll
        for (int o = 4; o > 0; o >>= 1)
            v += __shfl_down_sync(0xffffffffu, v, o);
        if (lane == 0) d_partials[blockIdx.x] = v;
    }
}

// ---- K4: final losses -----------------------------------------------------
__global__ void vq_loss_kernel(float* __restrict__ out) {
    __shared__ float warpsum[32];
    int t = threadIdx.x;                 // 1024 threads
    float s = d_partials[t];
    int lane = t & 31, wid = t >> 5;
#pragma unroll
    for (int o = 16; o > 0; o >>= 1)
        s += __shfl_down_sync(0xffffffffu, s, o);
    if (lane == 0) warpsum[wid] = s;
    __syncthreads();
    if (wid == 0) {
        float v = warpsum[lane];
#pragma unroll
        for (int o = 16; o > 0; o >>= 1)
            v += __shfl_down_sync(0xffffffffu, v, o);
        if (lane == 0) {
            float loss = v / (float)(N_ROWS * CDIM);
            out[(size_t)N_ROWS * CDIM + 0] = loss;   // vq_loss
            out[(size_t)N_ROWS * CDIM + 1] = loss;   // commitment_loss
        }
    }
}

// ---- entry ----------------------------------------------------------------
extern "C" void kernel_launch(void* const* d_in, const int* in_sizes, int n_in,
                              void* d_out, int out_size) {
    const float* z   = (const float*)d_in[0];
    const float* emb = (const float*)d_in[1];
    if (n_in >= 2 && in_sizes[0] == KCODES * CDIM && in_sizes[1] == N_ROWS * CDIM) {
        const float* t = z; z = emb; emb = t;
    }
    float* out = (float*)d_out;

    vq_prep_codes<<<KCODES / 256, 256>>>(emb);
    vq_prep_rows<<<N_ROWS / 256, 256>>>(z);
    vq_argmin_kernel<<<GRID_MAIN, CTA_MAIN>>>(z);
    vq_resolve<<<N_ROWS / 8, 256>>>(z, emb);
    vq_output_kernel<<<N_ROWS * 8 / 256, 256>>>(z, emb, out);
    vq_loss_kernel<<<1, 1024>>>(out);
    (void)out_size;
}

// round 10
// speedup vs baseline: 4.7376x; 4.7376x over previous
#include <cuda_runtime.h>
#include <cstdint>

// ---------------------------------------------------------------------------
// VectorQuantizer — TF32 tensor-core filter + bit-exact rescue.
//   Exact semantics (validated R6/R7, rel_err 0.0):
//     m  = exact fp32 FFMA dot (ascending), c = butterfly ||z||^2,
//     d2 = fl(fma(m,-2,c)) + e2, argmin = first index, q_st = fl(z+fl(q-z))
//   Filter: mma.m16n8k8.tf32 proxy p = fl(fma(m~,-2,c)); per-128-code chunk
//     min tracked via chunk-max(m~). Rescue chunks with p_min <= gmin + 2E,
//     E = s1*emax*2^-8 + 1e-5 (rigorous tf32 error bound, 2x margins).
//   Resolve: exact rescore of rescued chunks, (d2bits<<13|idx) key min.
// ---------------------------------------------------------------------------

#define N_ROWS  32768
#define CDIM    32
#define KCODES  8192
#define NCHUNK  64            // 64 chunks x 128 codes

#define NSPLIT_F 4            // filter code-splits (latency hiding)
#define ROWBLK_F 128          // 32768 / 256 rows per CTA

__device__ __align__(16) unsigned d_zpack[N_ROWS * CDIM];  // tf32 frag layout
__device__ __align__(16) unsigned d_epack[KCODES * CDIM];  // tf32 frag layout
__device__ __align__(16) float d_eT[CDIM * KCODES];        // eT[i][k] exact fp32
__device__ __align__(16) float d_e2[KCODES];               // butterfly ||e||^2
__device__ float d_c[N_ROWS];                              // butterfly ||z||^2
__device__ float d_s1[N_ROWS];                             // sum |z_i| (bound)
__device__ float d_chmin[(size_t)N_ROWS * NCHUNK];         // proxy chunk mins
__device__ int   d_emaxbits;                               // max |e| as int bits
__device__ int   d_idx[N_ROWS];
__device__ float d_partials[1024];

// ---- helpers --------------------------------------------------------------
__device__ __forceinline__ unsigned tf32_rn(float x) {
    unsigned r;
    asm("cvt.rn.tf32.f32 %0, %1;" : "=r"(r) : "f"(x));
    return r;
}
__device__ __forceinline__ float butterfly32(float* a) {
#pragma unroll
    for (int off = 16; off >= 1; off >>= 1)
#pragma unroll
        for (int i = 0; i < 16; i++)
            if (i < off) a[i] = __fadd_rn(a[i], a[i + off]);
    return a[0];
}
__device__ __forceinline__ void mma_tf32(float& d0, float& d1, float& d2, float& d3,
                                         unsigned a0, unsigned a1, unsigned a2, unsigned a3,
                                         unsigned b0, unsigned b1) {
    asm volatile(
        "mma.sync.aligned.m16n8k8.row.col.f32.tf32.tf32.f32 "
        "{%0,%1,%2,%3}, {%4,%5,%6,%7}, {%8,%9}, {%0,%1,%2,%3};"
        : "+f"(d0), "+f"(d1), "+f"(d2), "+f"(d3)
        : "r"(a0), "r"(a1), "r"(a2), "r"(a3), "r"(b0), "r"(b1));
}

// ---- P1: codes -> e2 (exact), eT, tf32 pack, emax -------------------------
__global__ void vq_prep_codes(const float* __restrict__ emb) {
    int k = blockIdx.x * blockDim.x + threadIdx.x;
    float e[CDIM], a[CDIM];
    const float4* er = (const float4*)(emb + (size_t)k * CDIM);
    float amax = 0.f;
#pragma unroll
    for (int j = 0; j < 8; j++) {
        float4 v = er[j];
        e[4 * j] = v.x; e[4 * j + 1] = v.y; e[4 * j + 2] = v.z; e[4 * j + 3] = v.w;
    }
#pragma unroll
    for (int i = 0; i < CDIM; i++) {
        a[i] = __fmul_rn(e[i], e[i]);
        amax = fmaxf(amax, fabsf(e[i]));
    }
    d_e2[k] = butterfly32(a);
#pragma unroll
    for (int i = 0; i < CDIM; i++) {
        d_eT[i * KCODES + k] = e[i];
        d_epack[(size_t)k * CDIM + (i & 3) * 8 + (i >> 2)] = tf32_rn(e[i]);
    }
#pragma unroll
    for (int off = 16; off >= 1; off >>= 1)
        amax = fmaxf(amax, __shfl_xor_sync(0xffffffffu, amax, off));
    if ((threadIdx.x & 31) == 0)
        atomicMax(&d_emaxbits, __float_as_int(amax));
}

// ---- P2: rows -> c (exact butterfly), s1, tf32 pack -----------------------
__global__ void vq_prep_rows(const float* __restrict__ z) {
    int n = blockIdx.x * blockDim.x + threadIdx.x;
    float zv[CDIM], a[CDIM];
    const float4* zr = (const float4*)(z + (size_t)n * CDIM);
    float s1 = 0.f;
#pragma unroll
    for (int j = 0; j < 8; j++) {
        float4 v = zr[j];
        zv[4 * j] = v.x; zv[4 * j + 1] = v.y; zv[4 * j + 2] = v.z; zv[4 * j + 3] = v.w;
    }
#pragma unroll
    for (int i = 0; i < CDIM; i++) {
        a[i] = __fmul_rn(zv[i], zv[i]);
        s1 += fabsf(zv[i]);
    }
    d_c[n] = butterfly32(a);
    d_s1[n] = s1;
#pragma unroll
    for (int i = 0; i < CDIM; i++)
        d_zpack[(size_t)n * CDIM + (i & 3) * 8 + (i >> 2)] = tf32_rn(zv[i]);
}

// ---- filter: TF32 mma proxy, per-chunk min (via chunk-max m~) -------------
// CTA: 256 thr = 8 warps x 32 rows. Grid: 128 rowblocks x NSPLIT_F.
__global__ __launch_bounds__(256) void vq_filter() {
    __shared__ uint4 s_b0[512];   // [q*32 + lane] fragment half 0 (16 KB)
    __shared__ uint4 s_b1[512];   // fragment half 1 (16 KB)

    int tid  = threadIdx.x;
    int lane = tid & 31;
    int wid  = tid >> 5;
    int gid  = lane >> 2;
    int tig  = lane & 3;
    int sp   = blockIdx.x / ROWBLK_F;
    int rb   = blockIdx.x % ROWBLK_F;
    int rowbase = rb * 256 + wid * 32;

    // A fragments: [tile][rowhalf][khalf] (layout validated R3)
    uint4 A[2][2][2];
#pragma unroll
    for (int t = 0; t < 2; t++) {
        int r0 = rowbase + t * 16 + gid;
        int r1 = r0 + 8;
        const uint4* p0 = (const uint4*)(d_zpack + (size_t)r0 * CDIM + tig * 8);
        const uint4* p1 = (const uint4*)(d_zpack + (size_t)r1 * CDIM + tig * 8);
        A[t][0][0] = p0[0]; A[t][0][1] = p0[1];
        A[t][1][0] = p1[0]; A[t][1][1] = p1[1];
    }
    float c0[2], c1[2];
#pragma unroll
    for (int t = 0; t < 2; t++) {
        c0[t] = d_c[rowbase + t * 16 + gid];
        c1[t] = d_c[rowbase + t * 16 + gid + 8];
    }

    for (int ch = sp * (NCHUNK / NSPLIT_F); ch < (sp + 1) * (NCHUNK / NSPLIT_F); ch++) {
        // stage B fragments for the chunk's 128 codes (16 sub-tiles of 8)
        for (int j = tid; j < 512; j += 256) {
            int q = j >> 5, ln = j & 31, g = ln >> 2, tg = ln & 3;
            const uint4* src = (const uint4*)(d_epack +
                (size_t)(ch * 128 + q * 8 + g) * CDIM + tg * 8);
            s_b0[j] = src[0];
            s_b1[j] = src[1];
        }
        __syncthreads();

        float ninf = __int_as_float(0xff800000);
        float mx[2][2] = {{ninf, ninf}, {ninf, ninf}};
#pragma unroll 4
        for (int q = 0; q < 16; q++) {
            uint4 B0 = s_b0[q * 32 + lane];
            uint4 B1 = s_b1[q * 32 + lane];
#pragma unroll
            for (int t = 0; t < 2; t++) {
                float d0 = 0.f, d1 = 0.f, d2 = 0.f, d3 = 0.f;
                mma_tf32(d0, d1, d2, d3, A[t][0][0].x, A[t][1][0].x, A[t][0][0].y, A[t][1][0].y, B0.x, B0.y);
                mma_tf32(d0, d1, d2, d3, A[t][0][0].z, A[t][1][0].z, A[t][0][0].w, A[t][1][0].w, B0.z, B0.w);
                mma_tf32(d0, d1, d2, d3, A[t][0][1].x, A[t][1][1].x, A[t][0][1].y, A[t][1][1].y, B1.x, B1.y);
                mma_tf32(d0, d1, d2, d3, A[t][0][1].z, A[t][1][1].z, A[t][0][1].w, A[t][1][1].w, B1.z, B1.w);
                mx[t][0] = fmaxf(mx[t][0], fmaxf(d0, d1));
                mx[t][1] = fmaxf(mx[t][1], fmaxf(d2, d3));
            }
        }
        // quad-reduce max m~ -> chunk-min proxy p = fl(fma(maxm,-2,c))
#pragma unroll
        for (int t = 0; t < 2; t++)
#pragma unroll
            for (int h = 0; h < 2; h++) {
                float v = mx[t][h];
                v = fmaxf(v, __shfl_xor_sync(0xffffffffu, v, 1));
                v = fmaxf(v, __shfl_xor_sync(0xffffffffu, v, 2));
                if (tig == 0) {
                    int row = rowbase + t * 16 + h * 8 + gid;
                    float cc = h ? c1[t] : c0[t];
                    d_chmin[(size_t)row * NCHUNK + ch] = __fmaf_rn(v, -2.0f, cc);
                }
            }
        __syncthreads();
    }
}

// ---- resolve: exact rescore of rescued chunks -----------------------------
// One warp per row; CTA 256 thr = 8 rows; grid 4096.
__global__ __launch_bounds__(256) void vq_resolve(const float* __restrict__ z) {
    __shared__ float s_chm[8][NCHUNK];
    int lane = threadIdx.x & 31;
    int warp = threadIdx.x >> 5;
    int row  = blockIdx.x * 8 + warp;

    float2 cm = ((const float2*)(d_chmin + (size_t)row * NCHUNK))[lane];
    s_chm[warp][2 * lane]     = cm.x;
    s_chm[warp][2 * lane + 1] = cm.y;
    float g = fminf(cm.x, cm.y);
#pragma unroll
    for (int off = 16; off >= 1; off >>= 1)
        g = fminf(g, __shfl_xor_sync(0xffffffffu, g, off));

    float emax = __int_as_float(d_emaxbits);
    float E = __fmaf_rn(d_s1[row], emax * 0.00390625f /*2^-8*/, 1e-5f);
    float thresh = g + 2.0f * E;

    float zv[CDIM];
    const float4* zr = (const float4*)(z + (size_t)row * CDIM);
#pragma unroll
    for (int j = 0; j < 8; j++) {
        float4 v = zr[j];
        zv[4 * j] = v.x; zv[4 * j + 1] = v.y; zv[4 * j + 2] = v.z; zv[4 * j + 3] = v.w;
    }
    float c = d_c[row];

    unsigned long long key = 0xFFFFFFFFFFFFFFFFull;
    for (int ch = 0; ch < NCHUNK; ch++) {
        if (s_chm[warp][ch] <= thresh) {
            float4 e2v = ((const float4*)(d_e2 + ch * 128))[lane];
            float m0 = 0.f, m1 = 0.f, m2 = 0.f, m3 = 0.f;
#pragma unroll
            for (int i = 0; i < CDIM; i++) {   // exact ascending FFMA chains
                float4 ev = ((const float4*)(d_eT + (size_t)i * KCODES + ch * 128))[lane];
                m0 = __fmaf_rn(zv[i], ev.x, m0);
                m1 = __fmaf_rn(zv[i], ev.y, m1);
                m2 = __fmaf_rn(zv[i], ev.z, m2);
                m3 = __fmaf_rn(zv[i], ev.w, m3);
            }
            int k0 = ch * 128 + lane * 4;
            float da = __fadd_rn(__fmaf_rn(m0, -2.0f, c), e2v.x);
            float db = __fadd_rn(__fmaf_rn(m1, -2.0f, c), e2v.y);
            float dc = __fadd_rn(__fmaf_rn(m2, -2.0f, c), e2v.z);
            float dd = __fadd_rn(__fmaf_rn(m3, -2.0f, c), e2v.w);
            unsigned long long ka = ((unsigned long long)__float_as_uint(da) << 13) | (unsigned)k0;
            unsigned long long kb = ((unsigned long long)__float_as_uint(db) << 13) | (unsigned)(k0 + 1);
            unsigned long long kc = ((unsigned long long)__float_as_uint(dc) << 13) | (unsigned)(k0 + 2);
            unsigned long long kd = ((unsigned long long)__float_as_uint(dd) << 13) | (unsigned)(k0 + 3);
            ka = ka < kb ? ka : kb;
            kc = kc < kd ? kc : kd;
            ka = ka < kc ? ka : kc;
            key = key < ka ? key : ka;
        }
    }
#pragma unroll
    for (int off = 16; off >= 1; off >>= 1) {
        unsigned long long o = __shfl_xor_sync(0xffffffffu, key, off);
        if (o < key) key = o;
    }
    if (lane == 0) d_idx[row] = (int)(key & 0x1FFFull);
}

// ---- K3: 8 threads/row — q_st, idx, loss partials -------------------------
__global__ void vq_output_kernel(const float* __restrict__ z,
                                 const float* __restrict__ emb,
                                 float* __restrict__ out) {
    __shared__ float warpsum[8];
    int gt = blockIdx.x * 256 + threadIdx.x;
    int n = gt >> 3, j = gt & 7;
    int k = d_idx[n];
    float4 e = ((const float4*)(emb + (size_t)k * CDIM))[j];
    float4 zv = ((const float4*)(z + (size_t)n * CDIM))[j];
    float dx = __fadd_rn(e.x, -zv.x), dy = __fadd_rn(e.y, -zv.y);
    float dz = __fadd_rn(e.z, -zv.z), dw = __fadd_rn(e.w, -zv.w);
    float4 q;
    q.x = __fadd_rn(zv.x, dx); q.y = __fadd_rn(zv.y, dy);
    q.z = __fadd_rn(zv.z, dz); q.w = __fadd_rn(zv.w, dw);
    ((float4*)(out + (size_t)n * CDIM))[j] = q;
    if (j == 0) out[(size_t)N_ROWS * CDIM + 2 + n] = (float)k;

    float s = dx * dx + dy * dy + dz * dz + dw * dw;
    int lane = threadIdx.x & 31, wid = threadIdx.x >> 5;
#pragma unroll
    for (int o = 16; o > 0; o >>= 1)
        s += __shfl_down_sync(0xffffffffu, s, o);
    if (lane == 0) warpsum[wid] = s;
    __syncthreads();
    if (wid == 0) {
        float v = (lane < 8) ? warpsum[lane] : 0.f;
#pragma unroll
        for (int o = 4; o > 0; o >>= 1)
            v += __shfl_down_sync(0xffffffffu, v, o);
        if (lane == 0) d_partials[blockIdx.x] = v;
    }
}

// ---- K4: final losses -----------------------------------------------------
__global__ void vq_loss_kernel(float* __restrict__ out) {
    __shared__ float warpsum[32];
    int t = threadIdx.x;                 // 1024 threads
    float s = d_partials[t];
    int lane = t & 31, wid = t >> 5;
#pragma unroll
    for (int o = 16; o > 0; o >>= 1)
        s += __shfl_down_sync(0xffffffffu, s, o);
    if (lane == 0) warpsum[wid] = s;
    __syncthreads();
    if (wid == 0) {
        float v = warpsum[lane];
#pragma unroll
        for (int o = 16; o > 0; o >>= 1)
            v += __shfl_down_sync(0xffffffffu, v, o);
        if (lane == 0) {
            float loss = v / (float)(N_ROWS * CDIM);
            out[(size_t)N_ROWS * CDIM + 0] = loss;   // vq_loss
            out[(size_t)N_ROWS * CDIM + 1] = loss;   // commitment_loss
        }
    }
}

// ---- entry ----------------------------------------------------------------
extern "C" void kernel_launch(void* const* d_in, const int* in_sizes, int n_in,
                              void* d_out, int out_size) {
    const float* z   = (const float*)d_in[0];
    const float* emb = (const float*)d_in[1];
    if (n_in >= 2 && in_sizes[0] == KCODES * CDIM && in_sizes[1] == N_ROWS * CDIM) {
        const float* t = z; z = emb; emb = t;
    }
    float* out = (float*)d_out;

    vq_prep_codes<<<KCODES / 256, 256>>>(emb);
    vq_prep_rows<<<N_ROWS / 256, 256>>>(z);
    vq_filter<<<ROWBLK_F * NSPLIT_F, 256>>>();
    vq_resolve<<<N_ROWS / 8, 256>>>(z);
    vq_output_kernel<<<N_ROWS * 8 / 256, 256>>>(z, emb, out);
    vq_loss_kernel<<<1, 1024>>>(out);
    (void)out_size;
}

// round 12
// speedup vs baseline: 5.3285x; 1.1247x over previous
#include <cuda_runtime.h>
#include <cstdint>

// ---------------------------------------------------------------------------
// VectorQuantizer — TF32 tensor-core filter + bit-exact rescue (R10: rel 0.0).
//   Exact semantics: m = exact fp32 FFMA dot (ascending), c = butterfly ||z||^2,
//   d2 = fl(fma(m,-2,c)) + e2, argmin = first index, q_st = fl(z + fl(q-z)).
//   Filter: mma.m16n8k8.tf32 proxy; per-128-code chunk min via chunk-max(m~).
//   Rescue: chunks with proxy <= gmin + 2E, E = s1*emax*2^-8 + 1e-5.
// R11 (resubmitted after infra failure): resolve scan -> ballot bitmasks;
//      output fused into resolve (z already in registers); prep merged.
// ---------------------------------------------------------------------------

#define N_ROWS  32768
#define CDIM    32
#define KCODES  8192
#define NCHUNK  64            // 64 chunks x 128 codes

#define NSPLIT_F 4            // filter code-splits (latency hiding)
#define ROWBLK_F 128          // 32768 / 256 rows per CTA

__device__ __align__(16) unsigned d_zpack[N_ROWS * CDIM];  // tf32 frag layout
__device__ __align__(16) unsigned d_epack[KCODES * CDIM];  // tf32 frag layout
__device__ __align__(16) float d_eT[CDIM * KCODES];        // eT[i][k] exact fp32
__device__ __align__(16) float d_e2[KCODES];               // butterfly ||e||^2
__device__ float d_c[N_ROWS];                              // butterfly ||z||^2
__device__ float d_s1[N_ROWS];                             // sum |z_i| (bound)
__device__ float d_chmin[(size_t)N_ROWS * NCHUNK];         // proxy chunk mins
__device__ int   d_emaxbits;                               // max |e| as int bits
__device__ float d_partials[4096];

// ---- helpers --------------------------------------------------------------
__device__ __forceinline__ unsigned tf32_rn(float x) {
    unsigned r;
    asm("cvt.rn.tf32.f32 %0, %1;" : "=r"(r) : "f"(x));
    return r;
}
__device__ __forceinline__ float butterfly32(float* a) {
#pragma unroll
    for (int off = 16; off >= 1; off >>= 1)
#pragma unroll
        for (int i = 0; i < 16; i++)
            if (i < off) a[i] = __fadd_rn(a[i], a[i + off]);
    return a[0];
}
__device__ __forceinline__ void mma_tf32(float& d0, float& d1, float& d2, float& d3,
                                         unsigned a0, unsigned a1, unsigned a2, unsigned a3,
                                         unsigned b0, unsigned b1) {
    asm volatile(
        "mma.sync.aligned.m16n8k8.row.col.f32.tf32.tf32.f32 "
        "{%0,%1,%2,%3}, {%4,%5,%6,%7}, {%8,%9}, {%0,%1,%2,%3};"
        : "+f"(d0), "+f"(d1), "+f"(d2), "+f"(d3)
        : "r"(a0), "r"(a1), "r"(a2), "r"(a3), "r"(b0), "r"(b1));
}

// ---- P: merged prep (blocks 0..31 -> codes, 32..159 -> rows) --------------
__global__ void vq_prep(const float* __restrict__ emb, const float* __restrict__ z) {
    int b = blockIdx.x;
    if (b < KCODES / 256) {
        int k = b * 256 + threadIdx.x;
        float e[CDIM], a[CDIM];
        const float4* er = (const float4*)(emb + (size_t)k * CDIM);
        float amax = 0.f;
#pragma unroll
        for (int j = 0; j < 8; j++) {
            float4 v = er[j];
            e[4 * j] = v.x; e[4 * j + 1] = v.y; e[4 * j + 2] = v.z; e[4 * j + 3] = v.w;
        }
#pragma unroll
        for (int i = 0; i < CDIM; i++) {
            a[i] = __fmul_rn(e[i], e[i]);
            amax = fmaxf(amax, fabsf(e[i]));
        }
        d_e2[k] = butterfly32(a);
#pragma unroll
        for (int i = 0; i < CDIM; i++) {
            d_eT[i * KCODES + k] = e[i];
            d_epack[(size_t)k * CDIM + (i & 3) * 8 + (i >> 2)] = tf32_rn(e[i]);
        }
#pragma unroll
        for (int off = 16; off >= 1; off >>= 1)
            amax = fmaxf(amax, __shfl_xor_sync(0xffffffffu, amax, off));
        if ((threadIdx.x & 31) == 0)
            atomicMax(&d_emaxbits, __float_as_int(amax));
    } else {
        int n = (b - KCODES / 256) * 256 + threadIdx.x;
        float zv[CDIM], a[CDIM];
        const float4* zr = (const float4*)(z + (size_t)n * CDIM);
        float s1 = 0.f;
#pragma unroll
        for (int j = 0; j < 8; j++) {
            float4 v = zr[j];
            zv[4 * j] = v.x; zv[4 * j + 1] = v.y; zv[4 * j + 2] = v.z; zv[4 * j + 3] = v.w;
        }
#pragma unroll
        for (int i = 0; i < CDIM; i++) {
            a[i] = __fmul_rn(zv[i], zv[i]);
            s1 += fabsf(zv[i]);
        }
        d_c[n] = butterfly32(a);
        d_s1[n] = s1;
#pragma unroll
        for (int i = 0; i < CDIM; i++)
            d_zpack[(size_t)n * CDIM + (i & 3) * 8 + (i >> 2)] = tf32_rn(zv[i]);
    }
}

// ---- filter: TF32 mma proxy, per-chunk min (via chunk-max m~) -------------
// CTA: 256 thr = 8 warps x 32 rows. Grid: 128 rowblocks x NSPLIT_F.
__global__ __launch_bounds__(256) void vq_filter() {
    __shared__ uint4 s_b0[512];   // [q*32 + lane] fragment half 0 (16 KB)
    __shared__ uint4 s_b1[512];   // fragment half 1 (16 KB)

    int tid  = threadIdx.x;
    int lane = tid & 31;
    int wid  = tid >> 5;
    int gid  = lane >> 2;
    int tig  = lane & 3;
    int sp   = blockIdx.x / ROWBLK_F;
    int rb   = blockIdx.x % ROWBLK_F;
    int rowbase = rb * 256 + wid * 32;

    // A fragments: [tile][rowhalf][khalf] (layout validated R3)
    uint4 A[2][2][2];
#pragma unroll
    for (int t = 0; t < 2; t++) {
        int r0 = rowbase + t * 16 + gid;
        int r1 = r0 + 8;
        const uint4* p0 = (const uint4*)(d_zpack + (size_t)r0 * CDIM + tig * 8);
        const uint4* p1 = (const uint4*)(d_zpack + (size_t)r1 * CDIM + tig * 8);
        A[t][0][0] = p0[0]; A[t][0][1] = p0[1];
        A[t][1][0] = p1[0]; A[t][1][1] = p1[1];
    }
    float c0[2], c1[2];
#pragma unroll
    for (int t = 0; t < 2; t++) {
        c0[t] = d_c[rowbase + t * 16 + gid];
        c1[t] = d_c[rowbase + t * 16 + gid + 8];
    }

    for (int ch = sp * (NCHUNK / NSPLIT_F); ch < (sp + 1) * (NCHUNK / NSPLIT_F); ch++) {
        // stage B fragments for the chunk's 128 codes (16 sub-tiles of 8)
        for (int j = tid; j < 512; j += 256) {
            int q = j >> 5, ln = j & 31, g = ln >> 2, tg = ln & 3;
            const uint4* src = (const uint4*)(d_epack +
                (size_t)(ch * 128 + q * 8 + g) * CDIM + tg * 8);
            s_b0[j] = src[0];
            s_b1[j] = src[1];
        }
        __syncthreads();

        float ninf = __int_as_float(0xff800000);
        float mx[2][2] = {{ninf, ninf}, {ninf, ninf}};
#pragma unroll 4
        for (int q = 0; q < 16; q++) {
            uint4 B0 = s_b0[q * 32 + lane];
            uint4 B1 = s_b1[q * 32 + lane];
#pragma unroll
            for (int t = 0; t < 2; t++) {
                float d0 = 0.f, d1 = 0.f, d2 = 0.f, d3 = 0.f;
                mma_tf32(d0, d1, d2, d3, A[t][0][0].x, A[t][1][0].x, A[t][0][0].y, A[t][1][0].y, B0.x, B0.y);
                mma_tf32(d0, d1, d2, d3, A[t][0][0].z, A[t][1][0].z, A[t][0][0].w, A[t][1][0].w, B0.z, B0.w);
                mma_tf32(d0, d1, d2, d3, A[t][0][1].x, A[t][1][1].x, A[t][0][1].y, A[t][1][1].y, B1.x, B1.y);
                mma_tf32(d0, d1, d2, d3, A[t][0][1].z, A[t][1][1].z, A[t][0][1].w, A[t][1][1].w, B1.z, B1.w);
                mx[t][0] = fmaxf(mx[t][0], fmaxf(d0, d1));
                mx[t][1] = fmaxf(mx[t][1], fmaxf(d2, d3));
            }
        }
        // quad-reduce max m~ -> chunk-min proxy p = fl(fma(maxm,-2,c))
#pragma unroll
        for (int t = 0; t < 2; t++)
#pragma unroll
            for (int h = 0; h < 2; h++) {
                float v = mx[t][h];
                v = fmaxf(v, __shfl_xor_sync(0xffffffffu, v, 1));
                v = fmaxf(v, __shfl_xor_sync(0xffffffffu, v, 2));
                if (tig == 0) {
                    int row = rowbase + t * 16 + h * 8 + gid;
                    float cc = h ? c1[t] : c0[t];
                    d_chmin[(size_t)row * NCHUNK + ch] = __fmaf_rn(v, -2.0f, cc);
                }
            }
        __syncthreads();
    }
}

// ---- resolve + output: exact rescore of rescued chunks, fused epilogue ----
// One warp per row; CTA 256 thr = 8 rows; grid 4096.
__global__ __launch_bounds__(256) void vq_resolve(const float* __restrict__ z,
                                                  const float* __restrict__ emb,
                                                  float* __restrict__ out) {
    __shared__ float warpsum[8];
    int lane = threadIdx.x & 31;
    int warp = threadIdx.x >> 5;
    int row  = blockIdx.x * 8 + warp;

    // lane l holds proxies of chunks 2l and 2l+1
    float2 cm = ((const float2*)(d_chmin + (size_t)row * NCHUNK))[lane];
    float g = fminf(cm.x, cm.y);
#pragma unroll
    for (int off = 16; off >= 1; off >>= 1)
        g = fminf(g, __shfl_xor_sync(0xffffffffu, g, off));

    float emax = __int_as_float(d_emaxbits);
    float E = __fmaf_rn(d_s1[row], emax * 0.00390625f /*2^-8*/, 1e-5f);
    float thresh = g + 2.0f * E;

    unsigned msk0 = __ballot_sync(0xffffffffu, cm.x <= thresh);  // chunks 2l
    unsigned msk1 = __ballot_sync(0xffffffffu, cm.y <= thresh);  // chunks 2l+1

    float zv[CDIM];
    const float4* zr = (const float4*)(z + (size_t)row * CDIM);
#pragma unroll
    for (int j = 0; j < 8; j++) {
        float4 v = zr[j];
        zv[4 * j] = v.x; zv[4 * j + 1] = v.y; zv[4 * j + 2] = v.z; zv[4 * j + 3] = v.w;
    }
    float c = d_c[row];

    unsigned long long key = 0xFFFFFFFFFFFFFFFFull;
    while (msk0 | msk1) {                  // uniform across warp (ballot masks)
        int ch;
        if (msk0) { int l = __ffs(msk0) - 1; msk0 &= msk0 - 1; ch = 2 * l; }
        else      { int l = __ffs(msk1) - 1; msk1 &= msk1 - 1; ch = 2 * l + 1; }

        float4 e2v = ((const float4*)(d_e2 + ch * 128))[lane];
        float m0 = 0.f, m1 = 0.f, m2 = 0.f, m3 = 0.f;
#pragma unroll
        for (int i = 0; i < CDIM; i++) {   // exact ascending FFMA chains
            float4 ev = ((const float4*)(d_eT + (size_t)i * KCODES + ch * 128))[lane];
            m0 = __fmaf_rn(zv[i], ev.x, m0);
            m1 = __fmaf_rn(zv[i], ev.y, m1);
            m2 = __fmaf_rn(zv[i], ev.z, m2);
            m3 = __fmaf_rn(zv[i], ev.w, m3);
        }
        int k0 = ch * 128 + lane * 4;
        float da = __fadd_rn(__fmaf_rn(m0, -2.0f, c), e2v.x);
        float db = __fadd_rn(__fmaf_rn(m1, -2.0f, c), e2v.y);
        float dc = __fadd_rn(__fmaf_rn(m2, -2.0f, c), e2v.z);
        float dd = __fadd_rn(__fmaf_rn(m3, -2.0f, c), e2v.w);
        unsigned long long ka = ((unsigned long long)__float_as_uint(da) << 13) | (unsigned)k0;
        unsigned long long kb = ((unsigned long long)__float_as_uint(db) << 13) | (unsigned)(k0 + 1);
        unsigned long long kc = ((unsigned long long)__float_as_uint(dc) << 13) | (unsigned)(k0 + 2);
        unsigned long long kd = ((unsigned long long)__float_as_uint(dd) << 13) | (unsigned)(k0 + 3);
        ka = ka < kb ? ka : kb;
        kc = kc < kd ? kc : kd;
        ka = ka < kc ? ka : kc;
        key = key < ka ? key : ka;
    }
#pragma unroll
    for (int off = 16; off >= 1; off >>= 1) {
        unsigned long long o = __shfl_xor_sync(0xffffffffu, key, off);
        if (o < key) key = o;
    }
    int k = (int)(key & 0x1FFFull);

    // fused output: lanes 0..7 write q_st row (z already in registers)
    float s = 0.f;
    if (lane < 8) {
        float4 e = ((const float4*)(emb + (size_t)k * CDIM))[lane];
        float z0 = zv[4 * lane], z1 = zv[4 * lane + 1];
        float z2 = zv[4 * lane + 2], z3 = zv[4 * lane + 3];
        float dx = __fadd_rn(e.x, -z0), dy = __fadd_rn(e.y, -z1);
        float dz = __fadd_rn(e.z, -z2), dw = __fadd_rn(e.w, -z3);
        float4 q;
        q.x = __fadd_rn(z0, dx); q.y = __fadd_rn(z1, dy);
        q.z = __fadd_rn(z2, dz); q.w = __fadd_rn(z3, dw);
        ((float4*)(out + (size_t)row * CDIM))[lane] = q;
        s = dx * dx + dy * dy + dz * dz + dw * dw;
        if (lane == 0) out[(size_t)N_ROWS * CDIM + 2 + row] = (float)k;
    }
#pragma unroll
    for (int off = 16; off >= 1; off >>= 1)
        s += __shfl_down_sync(0xffffffffu, s, off);
    if (lane == 0) warpsum[warp] = s;
    __syncthreads();
    if (warp == 0) {
        float v = (lane < 8) ? warpsum[lane] : 0.f;
#pragma unroll
        for (int off = 4; off >= 1; off >>= 1)
            v += __shfl_down_sync(0xffffffffu, v, off);
        if (lane == 0) d_partials[blockIdx.x] = v;
    }
}

// ---- final losses ---------------------------------------------------------
__global__ void vq_loss_kernel(float* __restrict__ out) {
    __shared__ float warpsum[32];
    int t = threadIdx.x;                 // 1024 threads, 4096 partials
    float s = d_partials[t] + d_partials[t + 1024]
            + d_partials[t + 2048] + d_partials[t + 3072];
    int lane = t & 31, wid = t >> 5;
#pragma unroll
    for (int o = 16; o > 0; o >>= 1)
        s += __shfl_down_sync(0xffffffffu, s, o);
    if (lane == 0) warpsum[wid] = s;
    __syncthreads();
    if (wid == 0) {
        float v = warpsum[lane];
#pragma unroll
        for (int o = 16; o > 0; o >>= 1)
            v += __shfl_down_sync(0xffffffffu, v, o);
        if (lane == 0) {
            float loss = v / (float)(N_ROWS * CDIM);
            out[(size_t)N_ROWS * CDIM + 0] = loss;   // vq_loss
            out[(size_t)N_ROWS * CDIM + 1] = loss;   // commitment_loss
        }
    }
}

// ---- entry ----------------------------------------------------------------
extern "C" void kernel_launch(void* const* d_in, const int* in_sizes, int n_in,
                              void* d_out, int out_size) {
    const float* z   = (const float*)d_in[0];
    const float* emb = (const float*)d_in[1];
    if (n_in >= 2 && in_sizes[0] == KCODES * CDIM && in_sizes[1] == N_ROWS * CDIM) {
        const float* t = z; z = emb; emb = t;
    }
    float* out = (float*)d_out;

    vq_prep<<<KCODES / 256 + N_ROWS / 256, 256>>>(emb, z);
    vq_filter<<<ROWBLK_F * NSPLIT_F, 256>>>();
    vq_resolve<<<N_ROWS / 8, 256>>>(z, emb, out);
    vq_loss_kernel<<<1, 1024>>>(out);
    (void)out_size;
}

// round 13
// speedup vs baseline: 6.0367x; 1.1329x over previous
#include <cuda_runtime.h>
#include <cstdint>

// ---------------------------------------------------------------------------
// VectorQuantizer — BF16 tensor-core filter + bit-exact rescue.
//   Exact semantics (validated R6..R12): m = exact fp32 FFMA dot (ascending),
//   c = butterfly ||z||^2, d2 = fl(fma(m,-2,c)) + e2, argmin = first index,
//   q_st = fl(z + fl(q - z)).
//   Filter: mma.m16n8k16.bf16 proxy (R13: was tf32 k8 — halves tensor time);
//   per-128-code chunk min via chunk-max(m~).
//   Rescue: chunks with proxy <= gmin + 2E, E = s1*emax*2^-6 + 1e-5
//   (rigorous bf16 bound with 2x margin).
// ---------------------------------------------------------------------------

#define N_ROWS  32768
#define CDIM    32
#define KCODES  8192
#define NCHUNK  64            // 64 chunks x 128 codes
#define WPR     16            // bf16 words per row (32 elems / 2)

#define NSPLIT_F 4            // filter code-splits (latency hiding)
#define ROWBLK_F 128          // 32768 / 256 rows per CTA

__device__ __align__(16) unsigned d_zpackb[N_ROWS * WPR];  // bf16x2 frag words
__device__ __align__(16) unsigned d_epackb[KCODES * WPR];  // bf16x2 frag words
__device__ __align__(16) float d_eT[CDIM * KCODES];        // eT[i][k] exact fp32
__device__ __align__(16) float d_e2[KCODES];               // butterfly ||e||^2
__device__ float d_c[N_ROWS];                              // butterfly ||z||^2
__device__ float d_s1[N_ROWS];                             // sum |z_i| (bound)
__device__ float d_chmin[(size_t)N_ROWS * NCHUNK];         // proxy chunk mins
__device__ int   d_emaxbits;                               // max |e| as int bits
__device__ float d_partials[4096];

// ---- helpers --------------------------------------------------------------
__device__ __forceinline__ unsigned bf16x2_rn(float hi, float lo) {
    unsigned w;   // low half = lo (even k), high half = hi (odd k)
    asm("cvt.rn.bf16x2.f32 %0, %1, %2;" : "=r"(w) : "f"(hi), "f"(lo));
    return w;
}
__device__ __forceinline__ float butterfly32(float* a) {
#pragma unroll
    for (int off = 16; off >= 1; off >>= 1)
#pragma unroll
        for (int i = 0; i < 16; i++)
            if (i < off) a[i] = __fadd_rn(a[i], a[i + off]);
    return a[0];
}
__device__ __forceinline__ void mma_bf16(float& d0, float& d1, float& d2, float& d3,
                                         unsigned a0, unsigned a1, unsigned a2, unsigned a3,
                                         unsigned b0, unsigned b1) {
    asm volatile(
        "mma.sync.aligned.m16n8k16.row.col.f32.bf16.bf16.f32 "
        "{%0,%1,%2,%3}, {%4,%5,%6,%7}, {%8,%9}, {%0,%1,%2,%3};"
        : "+f"(d0), "+f"(d1), "+f"(d2), "+f"(d3)
        : "r"(a0), "r"(a1), "r"(a2), "r"(a3), "r"(b0), "r"(b1));
}

// ---- P: merged prep (blocks 0..31 -> codes, rest -> rows) -----------------
// word p = {bf16(x[2p]), bf16(x[2p+1])} stored at (p&3)*4 + (p>>2), so a
// uint4 at tig*4 yields words {tig, tig+4, tig+8, tig+12} = the lane's
// {a0(q0), a2(q0), a0(q1), a2(q1)} (A) or {b0(q0), b1(q0), b0(q1), b1(q1)} (B).
__global__ void vq_prep(const float* __restrict__ emb, const float* __restrict__ z) {
    int b = blockIdx.x;
    if (b < KCODES / 256) {
        int k = b * 256 + threadIdx.x;
        float e[CDIM], a[CDIM];
        const float4* er = (const float4*)(emb + (size_t)k * CDIM);
        float amax = 0.f;
#pragma unroll
        for (int j = 0; j < 8; j++) {
            float4 v = er[j];
            e[4 * j] = v.x; e[4 * j + 1] = v.y; e[4 * j + 2] = v.z; e[4 * j + 3] = v.w;
        }
#pragma unroll
        for (int i = 0; i < CDIM; i++) {
            a[i] = __fmul_rn(e[i], e[i]);
            amax = fmaxf(amax, fabsf(e[i]));
        }
        d_e2[k] = butterfly32(a);
#pragma unroll
        for (int i = 0; i < CDIM; i++) d_eT[i * KCODES + k] = e[i];
#pragma unroll
        for (int p = 0; p < WPR; p++)
            d_epackb[(size_t)k * WPR + (p & 3) * 4 + (p >> 2)] =
                bf16x2_rn(e[2 * p + 1], e[2 * p]);
#pragma unroll
        for (int off = 16; off >= 1; off >>= 1)
            amax = fmaxf(amax, __shfl_xor_sync(0xffffffffu, amax, off));
        if ((threadIdx.x & 31) == 0)
            atomicMax(&d_emaxbits, __float_as_int(amax));
    } else {
        int n = (b - KCODES / 256) * 256 + threadIdx.x;
        float zv[CDIM], a[CDIM];
        const float4* zr = (const float4*)(z + (size_t)n * CDIM);
        float s1 = 0.f;
#pragma unroll
        for (int j = 0; j < 8; j++) {
            float4 v = zr[j];
            zv[4 * j] = v.x; zv[4 * j + 1] = v.y; zv[4 * j + 2] = v.z; zv[4 * j + 3] = v.w;
        }
#pragma unroll
        for (int i = 0; i < CDIM; i++) {
            a[i] = __fmul_rn(zv[i], zv[i]);
            s1 += fabsf(zv[i]);
        }
        d_c[n] = butterfly32(a);
        d_s1[n] = s1;
#pragma unroll
        for (int p = 0; p < WPR; p++)
            d_zpackb[(size_t)n * WPR + (p & 3) * 4 + (p >> 2)] =
                bf16x2_rn(zv[2 * p + 1], zv[2 * p]);
    }
}

// ---- filter: BF16 mma proxy, per-chunk min (via chunk-max m~) -------------
// CTA: 256 thr = 8 warps x 32 rows. Grid: 128 rowblocks x NSPLIT_F.
__global__ __launch_bounds__(256) void vq_filter() {
    __shared__ uint4 s_b[512];    // [q*32 + lane] all 4 B words (8 KB)

    int tid  = threadIdx.x;
    int lane = tid & 31;
    int wid  = tid >> 5;
    int gid  = lane >> 2;
    int tig  = lane & 3;
    int sp   = blockIdx.x / ROWBLK_F;
    int rb   = blockIdx.x % ROWBLK_F;
    int rowbase = rb * 256 + wid * 32;

    // A fragments: [tile][rowhalf] one uint4 = both k-chunks
    uint4 A[2][2];
#pragma unroll
    for (int t = 0; t < 2; t++) {
        int r0 = rowbase + t * 16 + gid;
        A[t][0] = *(const uint4*)(d_zpackb + (size_t)r0 * WPR + tig * 4);
        A[t][1] = *(const uint4*)(d_zpackb + (size_t)(r0 + 8) * WPR + tig * 4);
    }
    float c0[2], c1[2];
#pragma unroll
    for (int t = 0; t < 2; t++) {
        c0[t] = d_c[rowbase + t * 16 + gid];
        c1[t] = d_c[rowbase + t * 16 + gid + 8];
    }

    for (int ch = sp * (NCHUNK / NSPLIT_F); ch < (sp + 1) * (NCHUNK / NSPLIT_F); ch++) {
        // stage B words: tile q (8 codes), lane ln -> code q*8+(ln>>2), word grp ln&3
        for (int j = tid; j < 512; j += 256) {
            int q = j >> 5, ln = j & 31;
            s_b[j] = *(const uint4*)(d_epackb +
                (size_t)(ch * 128 + q * 8 + (ln >> 2)) * WPR + (ln & 3) * 4);
        }
        __syncthreads();

        float ninf = __int_as_float(0xff800000);
        float mx[2][2] = {{ninf, ninf}, {ninf, ninf}};
#pragma unroll 4
        for (int q = 0; q < 16; q++) {
            uint4 B = s_b[q * 32 + lane];
#pragma unroll
            for (int t = 0; t < 2; t++) {
                float d0 = 0.f, d1 = 0.f, d2 = 0.f, d3 = 0.f;
                // k chunk 0 (k=0..15): a0=p0.x a1=p1.x a2=p0.y a3=p1.y, b0=B.x b1=B.y
                mma_bf16(d0, d1, d2, d3, A[t][0].x, A[t][1].x, A[t][0].y, A[t][1].y, B.x, B.y);
                // k chunk 1 (k=16..31)
                mma_bf16(d0, d1, d2, d3, A[t][0].z, A[t][1].z, A[t][0].w, A[t][1].w, B.z, B.w);
                mx[t][0] = fmaxf(mx[t][0], fmaxf(d0, d1));
                mx[t][1] = fmaxf(mx[t][1], fmaxf(d2, d3));
            }
        }
        // quad-reduce max m~ -> chunk-min proxy p = fl(fma(maxm,-2,c))
#pragma unroll
        for (int t = 0; t < 2; t++)
#pragma unroll
            for (int h = 0; h < 2; h++) {
                float v = mx[t][h];
                v = fmaxf(v, __shfl_xor_sync(0xffffffffu, v, 1));
                v = fmaxf(v, __shfl_xor_sync(0xffffffffu, v, 2));
                if (tig == 0) {
                    int row = rowbase + t * 16 + h * 8 + gid;
                    float cc = h ? c1[t] : c0[t];
                    d_chmin[(size_t)row * NCHUNK + ch] = __fmaf_rn(v, -2.0f, cc);
                }
            }
        __syncthreads();
    }
}

// ---- resolve + output: exact rescore of rescued chunks, fused epilogue ----
// One warp per row; CTA 256 thr = 8 rows; grid 4096.
__global__ __launch_bounds__(256) void vq_resolve(const float* __restrict__ z,
                                                  const float* __restrict__ emb,
                                                  float* __restrict__ out) {
    __shared__ float warpsum[8];
    int lane = threadIdx.x & 31;
    int warp = threadIdx.x >> 5;
    int row  = blockIdx.x * 8 + warp;

    // lane l holds proxies of chunks 2l and 2l+1
    float2 cm = ((const float2*)(d_chmin + (size_t)row * NCHUNK))[lane];
    float g = fminf(cm.x, cm.y);
#pragma unroll
    for (int off = 16; off >= 1; off >>= 1)
        g = fminf(g, __shfl_xor_sync(0xffffffffu, g, off));

    float emax = __int_as_float(d_emaxbits);
    float E = __fmaf_rn(d_s1[row], emax * 0.015625f /*2^-6*/, 1e-5f);
    float thresh = g + 2.0f * E;

    unsigned msk0 = __ballot_sync(0xffffffffu, cm.x <= thresh);  // chunks 2l
    unsigned msk1 = __ballot_sync(0xffffffffu, cm.y <= thresh);  // chunks 2l+1

    float zv[CDIM];
    const float4* zr = (const float4*)(z + (size_t)row * CDIM);
#pragma unroll
    for (int j = 0; j < 8; j++) {
        float4 v = zr[j];
        zv[4 * j] = v.x; zv[4 * j + 1] = v.y; zv[4 * j + 2] = v.z; zv[4 * j + 3] = v.w;
    }
    float c = d_c[row];

    unsigned long long key = 0xFFFFFFFFFFFFFFFFull;
    while (msk0 | msk1) {                  // uniform across warp (ballot masks)
        int ch;
        if (msk0) { int l = __ffs(msk0) - 1; msk0 &= msk0 - 1; ch = 2 * l; }
        else      { int l = __ffs(msk1) - 1; msk1 &= msk1 - 1; ch = 2 * l + 1; }

        float4 e2v = ((const float4*)(d_e2 + ch * 128))[lane];
        float m0 = 0.f, m1 = 0.f, m2 = 0.f, m3 = 0.f;
#pragma unroll
        for (int i = 0; i < CDIM; i++) {   // exact ascending FFMA chains
            float4 ev = ((const float4*)(d_eT + (size_t)i * KCODES + ch * 128))[lane];
            m0 = __fmaf_rn(zv[i], ev.x, m0);
            m1 = __fmaf_rn(zv[i], ev.y, m1);
            m2 = __fmaf_rn(zv[i], ev.z, m2);
            m3 = __fmaf_rn(zv[i], ev.w, m3);
        }
        int k0 = ch * 128 + lane * 4;
        float da = __fadd_rn(__fmaf_rn(m0, -2.0f, c), e2v.x);
        float db = __fadd_rn(__fmaf_rn(m1, -2.0f, c), e2v.y);
        float dc = __fadd_rn(__fmaf_rn(m2, -2.0f, c), e2v.z);
        float dd = __fadd_rn(__fmaf_rn(m3, -2.0f, c), e2v.w);
        unsigned long long ka = ((unsigned long long)__float_as_uint(da) << 13) | (unsigned)k0;
        unsigned long long kb = ((unsigned long long)__float_as_uint(db) << 13) | (unsigned)(k0 + 1);
        unsigned long long kc = ((unsigned long long)__float_as_uint(dc) << 13) | (unsigned)(k0 + 2);
        unsigned long long kd = ((unsigned long long)__float_as_uint(dd) << 13) | (unsigned)(k0 + 3);
        ka = ka < kb ? ka : kb;
        kc = kc < kd ? kc : kd;
        ka = ka < kc ? ka : kc;
        key = key < ka ? key : ka;
    }
#pragma unroll
    for (int off = 16; off >= 1; off >>= 1) {
        unsigned long long o = __shfl_xor_sync(0xffffffffu, key, off);
        if (o < key) key = o;
    }
    int k = (int)(key & 0x1FFFull);

    // fused output: lanes 0..7 write q_st row (z already in registers)
    float s = 0.f;
    if (lane < 8) {
        float4 e = ((const float4*)(emb + (size_t)k * CDIM))[lane];
        float z0 = zv[4 * lane], z1 = zv[4 * lane + 1];
        float z2 = zv[4 * lane + 2], z3 = zv[4 * lane + 3];
        float dx = __fadd_rn(e.x, -z0), dy = __fadd_rn(e.y, -z1);
        float dz = __fadd_rn(e.z, -z2), dw = __fadd_rn(e.w, -z3);
        float4 q;
        q.x = __fadd_rn(z0, dx); q.y = __fadd_rn(z1, dy);
        q.z = __fadd_rn(z2, dz); q.w = __fadd_rn(z3, dw);
        ((float4*)(out + (size_t)row * CDIM))[lane] = q;
        s = dx * dx + dy * dy + dz * dz + dw * dw;
        if (lane == 0) out[(size_t)N_ROWS * CDIM + 2 + row] = (float)k;
    }
#pragma unroll
    for (int off = 16; off >= 1; off >>= 1)
        s += __shfl_down_sync(0xffffffffu, s, off);
    if (lane == 0) warpsum[warp] = s;
    __syncthreads();
    if (warp == 0) {
        float v = (lane < 8) ? warpsum[lane] : 0.f;
#pragma unroll
        for (int off = 4; off >= 1; off >>= 1)
            v += __shfl_down_sync(0xffffffffu, v, off);
        if (lane == 0) d_partials[blockIdx.x] = v;
    }
}

// ---- final losses ---------------------------------------------------------
__global__ void vq_loss_kernel(float* __restrict__ out) {
    __shared__ float warpsum[32];
    int t = threadIdx.x;                 // 1024 threads, 4096 partials
    float s = d_partials[t] + d_partials[t + 1024]
            + d_partials[t + 2048] + d_partials[t + 3072];
    int lane = t & 31, wid = t >> 5;
#pragma unroll
    for (int o = 16; o > 0; o >>= 1)
        s += __shfl_down_sync(0xffffffffu, s, o);
    if (lane == 0) warpsum[wid] = s;
    __syncthreads();
    if (wid == 0) {
        float v = warpsum[lane];
#pragma unroll
        for (int o = 16; o > 0; o >>= 1)
            v += __shfl_down_sync(0xffffffffu, v, o);
        if (lane == 0) {
            float loss = v / (float)(N_ROWS * CDIM);
            out[(size_t)N_ROWS * CDIM + 0] = loss;   // vq_loss
            out[(size_t)N_ROWS * CDIM + 1] = loss;   // commitment_loss
        }
    }
}

// ---- entry ----------------------------------------------------------------
extern "C" void kernel_launch(void* const* d_in, const int* in_sizes, int n_in,
                              void* d_out, int out_size) {
    const float* z   = (const float*)d_in[0];
    const float* emb = (const float*)d_in[1];
    if (n_in >= 2 && in_sizes[0] == KCODES * CDIM && in_sizes[1] == N_ROWS * CDIM) {
        const float* t = z; z = emb; emb = t;
    }
    float* out = (float*)d_out;

    vq_prep<<<KCODES / 256 + N_ROWS / 256, 256>>>(emb, z);
    vq_filter<<<ROWBLK_F * NSPLIT_F, 256>>>();
    vq_resolve<<<N_ROWS / 8, 256>>>(z, emb, out);
    vq_loss_kernel<<<1, 1024>>>(out);
    (void)out_size;
}